// round 11
// baseline (speedup 1.0000x reference)
#include <cuda_runtime.h>
#include <cuda_bf16.h>
#include <cstdint>

#define NN 100000
#define EE 600000
#define GG 256

// -------- scratch (device globals; no allocation allowed) --------
__device__ float g_x1[(size_t)NN * 128];
__device__ float g_lut[64 * 128];
__device__ __align__(16) unsigned short g_wbf[2 * 2 * 32768]; // [layer][hi/lo][h(128)][k(256)]
__device__ float g_pool[GG * 128];
__device__ float g_cnt[GG];
// CSR
__device__ int g_degi[NN];
__device__ int g_off[NN + 1];
__device__ int g_cur[NN];
__device__ int g_csr[EE];    // neighbor node id
__device__ int g_csrv[EE];   // neighbor vocab id (pre-resolved)
__device__ int g_bsum[128];
__device__ int g_bo[128];

// -------- helpers --------
__device__ __forceinline__ uint32_t smem_u32(const void* p) {
    uint32_t a;
    asm("{ .reg .u64 t; cvta.to.shared.u64 t, %1; cvt.u32.u64 %0, t; }" : "=r"(a) : "l"(p));
    return a;
}
__device__ __forceinline__ void warp_allred2(float& s, float& q) {
#pragma unroll
    for (int m = 16; m > 0; m >>= 1) {
        s += __shfl_xor_sync(0xffffffffu, s, m);
        q += __shfl_xor_sync(0xffffffffu, q, m);
    }
}
__device__ __forceinline__ void ldsm_x4(uint32_t& r0, uint32_t& r1, uint32_t& r2, uint32_t& r3,
                                        uint32_t addr) {
    asm volatile("ldmatrix.sync.aligned.m8n8.x4.shared.b16 {%0,%1,%2,%3}, [%4];"
                 : "=r"(r0), "=r"(r1), "=r"(r2), "=r"(r3) : "r"(addr));
}
__device__ __forceinline__ void mma16816(float* d, const uint32_t* a, uint32_t b0, uint32_t b1) {
    asm volatile("mma.sync.aligned.m16n8k16.row.col.f32.bf16.bf16.f32 "
                 "{%0,%1,%2,%3}, {%4,%5,%6,%7}, {%8,%9}, {%0,%1,%2,%3};"
                 : "+f"(d[0]), "+f"(d[1]), "+f"(d[2]), "+f"(d[3])
                 : "r"(a[0]), "r"(a[1]), "r"(a[2]), "r"(a[3]), "r"(b0), "r"(b1));
}

// ======== CSR build ========
__global__ void k_count(const int* __restrict__ dst, int e) {
    int i = blockIdx.x * blockDim.x + threadIdx.x;
    if (i < e) atomicAdd(&g_degi[dst[i]], 1);
}
__global__ void k_bsum(int n) {
    __shared__ int sh[1024];
    int i = blockIdx.x * 1024 + threadIdx.x;
    sh[threadIdx.x] = (i < n) ? g_degi[i] : 0;
    __syncthreads();
#pragma unroll
    for (int s = 512; s > 0; s >>= 1) {
        if (threadIdx.x < s) sh[threadIdx.x] += sh[threadIdx.x + s];
        __syncthreads();
    }
    if (threadIdx.x == 0) g_bsum[blockIdx.x] = sh[0];
}
__global__ void k_bscan(int nb, int n) {
    if (threadIdx.x == 0) {
        int run = 0;
        for (int b = 0; b < nb; b++) { g_bo[b] = run; run += g_bsum[b]; }
        g_off[n] = run;
    }
}
__global__ void k_scan(int n) {
    __shared__ int sh[1024];
    int tid = threadIdx.x;
    int i = blockIdx.x * 1024 + tid;
    int v = (i < n) ? g_degi[i] : 0;
    sh[tid] = v;
    __syncthreads();
#pragma unroll
    for (int d = 1; d < 1024; d <<= 1) {
        int t = (tid >= d) ? sh[tid - d] : 0;
        __syncthreads();
        sh[tid] += t;
        __syncthreads();
    }
    if (i < n) {
        int off = g_bo[blockIdx.x] + sh[tid] - v;
        g_off[i] = off;
        g_cur[i] = off;
    }
}
__global__ void k_fill(const int* __restrict__ src, const int* __restrict__ dst,
                       const int* __restrict__ xidx, int e) {
    int i = blockIdx.x * blockDim.x + threadIdx.x;
    if (i < e) {
        int s = src[i];
        int slot = atomicAdd(&g_cur[dst[i]], 1);
        g_csr[slot] = s;
        g_csrv[slot] = xidx[s];
    }
}

// -------- LN0 lookup table: lut[v] = layernorm(emb[v]) --------
__global__ void lut_kernel(const float* __restrict__ emb, const float* __restrict__ lng,
                           const float* __restrict__ lnb, float* __restrict__ lut) {
    int w = (blockIdx.x * blockDim.x + threadIdx.x) >> 5;
    int lane = threadIdx.x & 31;
    if (w >= 64) return;
    float4 e = *(const float4*)(emb + (size_t)w * 128 + lane * 4);
    float s = e.x + e.y + e.z + e.w;
    float q = e.x * e.x + e.y * e.y + e.z * e.z + e.w * e.w;
    warp_allred2(s, q);
    float mean = s * (1.0f / 128.0f);
    float var  = q * (1.0f / 128.0f) - mean * mean;
    float rs   = rsqrtf(var + 1e-5f);
    float4 g4 = *(const float4*)(lng + lane * 4);
    float4 b4 = *(const float4*)(lnb + lane * 4);
    float4 o;
    o.x = (e.x - mean) * rs * g4.x + b4.x;
    o.y = (e.y - mean) * rs * g4.y + b4.y;
    o.z = (e.z - mean) * rs * g4.z + b4.z;
    o.w = (e.w - mean) * rs * g4.w + b4.w;
    *(float4*)(lut + (size_t)w * 128 + lane * 4) = o;
}

// -------- graph-size counts --------
__global__ void cnt_kernel(const int* __restrict__ batch, float* __restrict__ cnt, int n) {
    int i = blockIdx.x * blockDim.x + threadIdx.x;
    if (i < n) atomicAdd(&cnt[batch[i]], 1.0f);
}

// -------- weight prep: bf16 hi/lo --------
__global__ void prep_wbf(const float* __restrict__ w0l, const float* __restrict__ w0r,
                         const float* __restrict__ w1l, const float* __restrict__ w1r,
                         unsigned short* __restrict__ wbf) {
    int i = blockIdx.x * blockDim.x + threadIdx.x;
    if (i >= 2 * 128 * 256) return;
    int layer = i >> 15;
    int rem = i & 32767;
    int h = rem >> 8;
    int d = rem & 255;
    const float* wl = layer ? w1l : w0l;
    const float* wr = layer ? w1r : w0r;
    float w = (d < 128) ? wl[h * 128 + d] : wr[h * 128 + (d - 128)];
    __nv_bfloat16 hi = __float2bfloat16(w);
    __nv_bfloat16 lo = __float2bfloat16(w - __bfloat162float(hi));
    size_t base = (size_t)layer * 65536 + (size_t)h * 256 + d;
    wbf[base]         = __bfloat16_as_ushort(hi);
    wbf[base + 32768] = __bfloat16_as_ushort(lo);
}

// ======== HMMA bf16x3 SAGE linear with FUSED gather, BM=64 x BN=128, 2 CTAs/SM ========
// half0 A = mean over CSR neighbors (mode0: lut rows via csrv; mode1: x rows via csr),
//           gathered in-kernel (warp per 8 tile rows), no agg intermediate.
// half1 A = lin_r operand (mode0: lut[x_idx[row]]; mode1: x row).
// mode 0 epilogue: LN1 -> out.   mode 1 epilogue: fused pool atomics (no out write).
#define ROWA 272
#define OFF_AHI    0
#define OFF_ALO    17408
#define OFF_BHI    34816
#define OFF_BLO    69632
#define OFF_MEAN   104448
#define OFF_RS     104704
#define OFF_GID    104960            // 64 ints
#define SMEM_TOTAL 105216

__global__ void __launch_bounds__(256, 2)
sage_mma(const float* __restrict__ xin,
         const int* __restrict__ xidx, const float* __restrict__ lut,
         const unsigned short* __restrict__ wbf, const float* __restrict__ bias,
         const float* __restrict__ lng, const float* __restrict__ lnb,
         float* __restrict__ out, const int* __restrict__ batch,
         float* __restrict__ pool, int n, int mode) {
    extern __shared__ char smem[];
    const uint32_t sb = smem_u32(smem);
    const int tid  = threadIdx.x;
    const int wid  = tid >> 5;
    const int lane = tid & 31;
    const int row0 = blockIdx.x * 64;
    const int wm   = wid & 1;
    const int wn   = wid >> 1;

    float acc[2][4][4];
#pragma unroll
    for (int mt = 0; mt < 2; mt++)
#pragma unroll
        for (int nt = 0; nt < 4; nt++)
#pragma unroll
            for (int j = 0; j < 4; j++) acc[mt][nt][j] = 0.f;

    const int lm = lane >> 3;
    const int lr = lane & 7;
    const uint32_t aRow = (uint32_t)(wm * 32 + (lm & 1) * 8 + lr);
    const uint32_t aKof = (uint32_t)((lm >> 1) * 16);
    const uint32_t bN   = (uint32_t)(wn * 32 + (lm >> 1) * 8 + lr);
    const uint32_t bKof = (uint32_t)((lm & 1) * 16);
    const float* gsrc = (mode == 0) ? lut : xin;
    const int* gidx = (mode == 0) ? g_csrv : g_csr;

#pragma unroll 1
    for (int half = 0; half < 2; half++) {
        // ---- fill B hi/lo for this K-half ----
#pragma unroll
        for (int it = 0; it < 16; it++) {
            int idx = it * 256 + tid;
            int part = idx >> 11;
            int rem = idx & 2047;
            int row = rem >> 4;
            int ch = rem & 15;
            uint4 v = *(const uint4*)(wbf + part * 32768 + row * 256 + half * 128 + ch * 8);
            *(uint4*)(smem + OFF_BHI + part * 34816 + row * ROWA + ch * 16) = v;
        }
        // ---- fill A hi/lo for this K-half ----
        if (half == 0) {
            // fused gather-mean: warp handles 8 tile rows
#pragma unroll 1
            for (int ri = 0; ri < 8; ri++) {
                int row = wid * 8 + ri;
                int node = row0 + row;
                float4 a0 = make_float4(0.f, 0.f, 0.f, 0.f);
                float4 a1 = make_float4(0.f, 0.f, 0.f, 0.f);
                if (node < n) {
                    int beg = __ldg(&g_off[node]);
                    int end = __ldg(&g_off[node + 1]);
                    for (int j0 = beg; j0 < end; j0 += 32) {
                        int id = 0;
                        if (j0 + lane < end) id = __ldg(&gidx[j0 + lane]);
                        int c = end - j0; if (c > 32) c = 32;
                        int t = 0;
                        for (; t + 1 < c; t += 2) {
                            int s0 = __shfl_sync(0xffffffffu, id, t);
                            int s1 = __shfl_sync(0xffffffffu, id, t + 1);
                            float4 v0 = *(const float4*)(gsrc + (size_t)s0 * 128 + lane * 4);
                            float4 v1 = *(const float4*)(gsrc + (size_t)s1 * 128 + lane * 4);
                            a0.x += v0.x; a0.y += v0.y; a0.z += v0.z; a0.w += v0.w;
                            a1.x += v1.x; a1.y += v1.y; a1.z += v1.z; a1.w += v1.w;
                        }
                        if (t < c) {
                            int s0 = __shfl_sync(0xffffffffu, id, t);
                            float4 v0 = *(const float4*)(gsrc + (size_t)s0 * 128 + lane * 4);
                            a0.x += v0.x; a0.y += v0.y; a0.z += v0.z; a0.w += v0.w;
                        }
                    }
                    float inv = 1.0f / fmaxf((float)(end - beg), 1.0f);
                    a0.x = (a0.x + a1.x) * inv; a0.y = (a0.y + a1.y) * inv;
                    a0.z = (a0.z + a1.z) * inv; a0.w = (a0.w + a1.w) * inv;
                }
                float hx = __bfloat162float(__float2bfloat16(a0.x));
                float hy = __bfloat162float(__float2bfloat16(a0.y));
                float hz = __bfloat162float(__float2bfloat16(a0.z));
                float hw = __bfloat162float(__float2bfloat16(a0.w));
                __nv_bfloat162 h0 = __floats2bfloat162_rn(hx, hy);
                __nv_bfloat162 h1 = __floats2bfloat162_rn(hz, hw);
                __nv_bfloat162 l0 = __floats2bfloat162_rn(a0.x - hx, a0.y - hy);
                __nv_bfloat162 l1 = __floats2bfloat162_rn(a0.z - hz, a0.w - hw);
                uint2 ph, pl;
                ph.x = *reinterpret_cast<unsigned*>(&h0);
                ph.y = *reinterpret_cast<unsigned*>(&h1);
                pl.x = *reinterpret_cast<unsigned*>(&l0);
                pl.y = *reinterpret_cast<unsigned*>(&l1);
                *(uint2*)(smem + OFF_AHI + row * ROWA + lane * 8) = ph;
                *(uint2*)(smem + OFF_ALO + row * ROWA + lane * 8) = pl;
            }
        } else {
            // lin_r operand: coalesced rows
#pragma unroll
            for (int it = 0; it < 8; it++) {
                int idx = it * 256 + tid;
                int row = idx >> 5;
                int col = (idx & 31) * 4;
                float4 v = make_float4(0.f, 0.f, 0.f, 0.f);
                int grow = row0 + row;
                if (grow < n) {
                    if (mode == 0) {
                        int vv = __ldg(xidx + grow);
                        v = *(const float4*)(lut + (size_t)vv * 128 + col);
                    } else {
                        v = *(const float4*)(xin + (size_t)grow * 128 + col);
                    }
                }
                float hx = __bfloat162float(__float2bfloat16(v.x));
                float hy = __bfloat162float(__float2bfloat16(v.y));
                float hz = __bfloat162float(__float2bfloat16(v.z));
                float hw = __bfloat162float(__float2bfloat16(v.w));
                __nv_bfloat162 h0 = __floats2bfloat162_rn(hx, hy);
                __nv_bfloat162 h1 = __floats2bfloat162_rn(hz, hw);
                __nv_bfloat162 l0 = __floats2bfloat162_rn(v.x - hx, v.y - hy);
                __nv_bfloat162 l1 = __floats2bfloat162_rn(v.z - hz, v.w - hw);
                uint2 ph, pl;
                ph.x = *reinterpret_cast<unsigned*>(&h0);
                ph.y = *reinterpret_cast<unsigned*>(&h1);
                pl.x = *reinterpret_cast<unsigned*>(&l0);
                pl.y = *reinterpret_cast<unsigned*>(&l1);
                *(uint2*)(smem + OFF_AHI + row * ROWA + col * 2) = ph;
                *(uint2*)(smem + OFF_ALO + row * ROWA + col * 2) = pl;
            }
        }
        __syncthreads();

        // ---- 8 k16-steps, 3 products ----
#pragma unroll
        for (int kk = 0; kk < 8; kk++) {
            const uint32_t kB = (uint32_t)kk * 32;
            const uint32_t aOff = aRow * ROWA + aKof + kB;
            const uint32_t bOff = bN * ROWA + bKof + kB;
            uint32_t ah[2][4], al[2][4], bh[2][4], bl[2][4];
#pragma unroll
            for (int mt = 0; mt < 2; mt++) {
                ldsm_x4(ah[mt][0], ah[mt][1], ah[mt][2], ah[mt][3],
                        sb + OFF_AHI + aOff + (uint32_t)mt * 16u * ROWA);
                ldsm_x4(al[mt][0], al[mt][1], al[mt][2], al[mt][3],
                        sb + OFF_ALO + aOff + (uint32_t)mt * 16u * ROWA);
            }
#pragma unroll
            for (int nb = 0; nb < 2; nb++) {
                ldsm_x4(bh[nb][0], bh[nb][1], bh[nb][2], bh[nb][3],
                        sb + OFF_BHI + bOff + (uint32_t)nb * 16u * ROWA);
                ldsm_x4(bl[nb][0], bl[nb][1], bl[nb][2], bl[nb][3],
                        sb + OFF_BLO + bOff + (uint32_t)nb * 16u * ROWA);
            }
#pragma unroll
            for (int mt = 0; mt < 2; mt++)
#pragma unroll
                for (int nb = 0; nb < 2; nb++) {
                    mma16816(acc[mt][nb * 2 + 0], ah[mt], bh[nb][0], bh[nb][1]);
                    mma16816(acc[mt][nb * 2 + 1], ah[mt], bh[nb][2], bh[nb][3]);
                    mma16816(acc[mt][nb * 2 + 0], ah[mt], bl[nb][0], bl[nb][1]);
                    mma16816(acc[mt][nb * 2 + 1], ah[mt], bl[nb][2], bl[nb][3]);
                    mma16816(acc[mt][nb * 2 + 0], al[mt], bh[nb][0], bh[nb][1]);
                    mma16816(acc[mt][nb * 2 + 1], al[mt], bh[nb][2], bh[nb][3]);
                }
        }
        __syncthreads();
    }

    // ---- stage: bias + relu into fp32 smem (stride 132, overlays A/B region) ----
    float* stage = (float*)smem;
    {
        const int cBase = wn * 32 + (lane & 3) * 2;
#pragma unroll
        for (int nt = 0; nt < 4; nt++) {
            int col = cBase + nt * 8;
            float b0 = __ldg(bias + col), b1 = __ldg(bias + col + 1);
#pragma unroll
            for (int mt = 0; mt < 2; mt++) {
                int r0 = wm * 32 + mt * 16 + (lane >> 2);
                float2 v0, v1;
                v0.x = fmaxf(acc[mt][nt][0] + b0, 0.f);
                v0.y = fmaxf(acc[mt][nt][1] + b1, 0.f);
                v1.x = fmaxf(acc[mt][nt][2] + b0, 0.f);
                v1.y = fmaxf(acc[mt][nt][3] + b1, 0.f);
                *(float2*)(stage + r0 * 132 + col)       = v0;
                *(float2*)(stage + (r0 + 8) * 132 + col) = v1;
            }
        }
    }
    if (mode == 1 && tid < 64) {
        int grow = row0 + tid;
        ((int*)(smem + OFF_GID))[tid] = (grow < n) ? __ldg(batch + grow) : -1;
    }
    __syncthreads();

    if (mode == 0) {
        // ---- LN stats per row ----
        if (tid < 64) {
            const float* rp = stage + tid * 132;
            float s = 0.f, q = 0.f;
#pragma unroll
            for (int c4 = 0; c4 < 32; c4++) {
                float4 v = *(const float4*)(rp + c4 * 4);
                s += v.x + v.y + v.z + v.w;
                q += v.x * v.x + v.y * v.y + v.z * v.z + v.w * v.w;
            }
            float mean = s * (1.0f / 128.0f);
            float var  = q * (1.0f / 128.0f) - mean * mean;
            ((float*)(smem + OFF_MEAN))[tid] = mean;
            ((float*)(smem + OFF_RS))[tid]   = rsqrtf(var + 1e-5f);
        }
        __syncthreads();
        const float* sMean = (const float*)(smem + OFF_MEAN);
        const float* sRs   = (const float*)(smem + OFF_RS);
#pragma unroll
        for (int it = 0; it < 8; it++) {
            int idx = it * 256 + tid;
            int row = idx >> 5;
            int col = (idx & 31) * 4;
            int grow = row0 + row;
            if (grow < n) {
                float4 v = *(const float4*)(stage + row * 132 + col);
                float m = sMean[row], r = sRs[row];
                float4 g4 = *(const float4*)(lng + col);
                float4 b4 = *(const float4*)(lnb + col);
                float4 o;
                o.x = (v.x - m) * r * g4.x + b4.x;
                o.y = (v.y - m) * r * g4.y + b4.y;
                o.z = (v.z - m) * r * g4.z + b4.z;
                o.w = (v.w - m) * r * g4.w + b4.w;
                *(float4*)(out + (size_t)grow * 128 + col) = o;
            }
        }
    } else {
        // ---- fused pooling: run-length over sorted batch within the tile ----
        if (tid < 128) {
            const int* sgid = (const int*)(smem + OFF_GID);
            float a = 0.f;
            int cur = sgid[0];
#pragma unroll 1
            for (int r = 0; r < 64; r++) {
                int gid = sgid[r];
                if (gid != cur) {
                    if (cur >= 0) atomicAdd(&pool[(size_t)cur * 128 + tid], a);
                    a = 0.f; cur = gid;
                }
                if (gid >= 0) a += stage[r * 132 + tid];
            }
            if (cur >= 0) atomicAdd(&pool[(size_t)cur * 128 + tid], a);
        }
    }
}

// -------- MLP head --------
__global__ void mlp_kernel(const float* __restrict__ sums, const float* __restrict__ cnts,
                           const float* __restrict__ w1, const float* __restrict__ b1,
                           const float* __restrict__ w2, const float* __restrict__ b2,
                           float* __restrict__ out) {
    __shared__ float sg[128];
    __shared__ float sh[64];
    int g = blockIdx.x;
    int t = threadIdx.x;   // 64
    float inv = 1.0f / fmaxf(__ldg(cnts + g), 1.0f);
    sg[t]      = sums[(size_t)g * 128 + t] * inv;
    sg[t + 64] = sums[(size_t)g * 128 + t + 64] * inv;
    __syncthreads();
    float h = b1[t];
#pragma unroll
    for (int d = 0; d < 128; d++) h += w1[t * 128 + d] * sg[d];
    sh[t] = fmaxf(h, 0.f);
    __syncthreads();
    if (t < 2) {
        float o = b2[t];
#pragma unroll
        for (int d = 0; d < 64; d++) o += w2[t * 64 + d] * sh[d];
        out[g * 2 + t] = o;
    }
}

// -------- launch --------
extern "C" void kernel_launch(void* const* d_in, const int* in_sizes, int n_in,
                              void* d_out, int out_size) {
    const int*   x_idx = (const int*)d_in[0];
    const int*   eidx  = (const int*)d_in[1];
    const int*   batch = (const int*)d_in[2];
    const float* emb   = (const float*)d_in[3];
    const float* ln0g  = (const float*)d_in[4];
    const float* ln0b  = (const float*)d_in[5];
    const float* w0l   = (const float*)d_in[6];
    const float* b0l   = (const float*)d_in[7];
    const float* w0r   = (const float*)d_in[8];
    const float* ln1g  = (const float*)d_in[9];
    const float* ln1b  = (const float*)d_in[10];
    const float* w1l   = (const float*)d_in[11];
    const float* b1l   = (const float*)d_in[12];
    const float* w1r   = (const float*)d_in[13];
    const float* mw1   = (const float*)d_in[14];
    const float* mb1   = (const float*)d_in[15];
    const float* mw2   = (const float*)d_in[16];
    const float* mb2   = (const float*)d_in[17];
    float* out = (float*)d_out;

    int n = in_sizes[0];
    int e = in_sizes[1] / 2;
    const int* src = eidx;
    const int* dst = eidx + e;

    float *x1, *lut, *pool, *cnt;
    unsigned short* wbf;
    int* degi;
    (void)cudaGetSymbolAddress((void**)&x1,   g_x1);
    (void)cudaGetSymbolAddress((void**)&lut,  g_lut);
    (void)cudaGetSymbolAddress((void**)&wbf,  g_wbf);
    (void)cudaGetSymbolAddress((void**)&pool, g_pool);
    (void)cudaGetSymbolAddress((void**)&cnt,  g_cnt);
    (void)cudaGetSymbolAddress((void**)&degi, g_degi);

    (void)cudaFuncSetAttribute(sage_mma, cudaFuncAttributeMaxDynamicSharedMemorySize,
                               SMEM_TOTAL);

    cudaMemsetAsync(degi, 0, (size_t)n * sizeof(int));
    cudaMemsetAsync(pool, 0, (size_t)GG * 128 * sizeof(float));
    cudaMemsetAsync(cnt,  0, (size_t)GG * sizeof(float));

    // CSR build (once; reused by both layers)
    int nb = (n + 1023) / 1024;
    k_count<<<(e + 255) / 256, 256>>>(dst, e);
    k_bsum<<<nb, 1024>>>(n);
    k_bscan<<<1, 32>>>(nb, n);
    k_scan<<<nb, 1024>>>(n);
    k_fill<<<(e + 255) / 256, 256>>>(src, dst, x_idx, e);

    prep_wbf<<<256, 256>>>(w0l, w0r, w1l, w1r, wbf);
    lut_kernel<<<8, 256>>>(emb, ln0g, ln0b, lut);
    cnt_kernel<<<(n + 255) / 256, 256>>>(batch, cnt, n);

    int gtiles = (n + 63) / 64;
    // layer 0: fused gather(LUT) + GEMM + LN1 -> x1
    sage_mma<<<gtiles, 256, SMEM_TOTAL>>>(nullptr, x_idx, lut, wbf, b0l,
                                          ln1g, ln1b, x1, nullptr, nullptr, n, 0);
    // layer 1: fused gather(x1) + GEMM + fused pooling
    sage_mma<<<gtiles, 256, SMEM_TOTAL>>>(x1, nullptr, nullptr, wbf + 65536, b1l,
                                          nullptr, nullptr, nullptr, batch, pool, n, 1);
    // head
    mlp_kernel<<<GG, 64>>>(pool, cnt, mw1, mb1, mw2, mb2, out);
}

// round 15
// speedup vs baseline: 1.4193x; 1.4193x over previous
#include <cuda_runtime.h>
#include <cuda_bf16.h>
#include <cstdint>

#define NN 100000
#define EE 600000
#define GG 256

// -------- scratch (device globals; no allocation allowed) --------
__device__ float g_x1[(size_t)NN * 128];
__device__ float g_agg[(size_t)NN * 128];
__device__ float g_lut[64 * 128];
__device__ float g_M[64 * 128];      // LUT @ w0l^T
__device__ float g_R[64 * 128];      // LUT @ w0r^T
__device__ __align__(16) unsigned short g_wbf[2 * 32768]; // layer1 [hi/lo][h(128)][k(256)]
__device__ float g_pool[GG * 128];
__device__ float g_cnt[GG];
// CSR
__device__ int g_degi[NN];
__device__ int g_off[NN + 1];
__device__ int g_cur[NN];
__device__ int g_csr[EE];    // neighbor node id
__device__ int g_csrv[EE];   // neighbor vocab id (pre-resolved)
__device__ int g_bsum[128];
__device__ int g_bo[128];

// -------- helpers --------
__device__ __forceinline__ uint32_t smem_u32(const void* p) {
    uint32_t a;
    asm("{ .reg .u64 t; cvta.to.shared.u64 t, %1; cvt.u32.u64 %0, t; }" : "=r"(a) : "l"(p));
    return a;
}
__device__ __forceinline__ void warp_allred2(float& s, float& q) {
#pragma unroll
    for (int m = 16; m > 0; m >>= 1) {
        s += __shfl_xor_sync(0xffffffffu, s, m);
        q += __shfl_xor_sync(0xffffffffu, q, m);
    }
}
__device__ __forceinline__ void ldsm_x4(uint32_t& r0, uint32_t& r1, uint32_t& r2, uint32_t& r3,
                                        uint32_t addr) {
    asm volatile("ldmatrix.sync.aligned.m8n8.x4.shared.b16 {%0,%1,%2,%3}, [%4];"
                 : "=r"(r0), "=r"(r1), "=r"(r2), "=r"(r3) : "r"(addr));
}
__device__ __forceinline__ void mma16816(float* d, const uint32_t* a, uint32_t b0, uint32_t b1) {
    asm volatile("mma.sync.aligned.m16n8k16.row.col.f32.bf16.bf16.f32 "
                 "{%0,%1,%2,%3}, {%4,%5,%6,%7}, {%8,%9}, {%0,%1,%2,%3};"
                 : "+f"(d[0]), "+f"(d[1]), "+f"(d[2]), "+f"(d[3])
                 : "r"(a[0]), "r"(a[1]), "r"(a[2]), "r"(a[3]), "r"(b0), "r"(b1));
}

// ======== CSR build ========
__global__ void k_count(const int* __restrict__ dst, int e) {
    int i = blockIdx.x * blockDim.x + threadIdx.x;
    if (i < e) atomicAdd(&g_degi[dst[i]], 1);
}
__global__ void k_bsum(int n) {
    __shared__ int sh[1024];
    int i = blockIdx.x * 1024 + threadIdx.x;
    sh[threadIdx.x] = (i < n) ? g_degi[i] : 0;
    __syncthreads();
#pragma unroll
    for (int s = 512; s > 0; s >>= 1) {
        if (threadIdx.x < s) sh[threadIdx.x] += sh[threadIdx.x + s];
        __syncthreads();
    }
    if (threadIdx.x == 0) g_bsum[blockIdx.x] = sh[0];
}
__global__ void k_bscan(int nb, int n) {
    if (threadIdx.x == 0) {
        int run = 0;
        for (int b = 0; b < nb; b++) { g_bo[b] = run; run += g_bsum[b]; }
        g_off[n] = run;
    }
}
__global__ void k_scan(int n) {
    __shared__ int sh[1024];
    int tid = threadIdx.x;
    int i = blockIdx.x * 1024 + tid;
    int v = (i < n) ? g_degi[i] : 0;
    sh[tid] = v;
    __syncthreads();
#pragma unroll
    for (int d = 1; d < 1024; d <<= 1) {
        int t = (tid >= d) ? sh[tid - d] : 0;
        __syncthreads();
        sh[tid] += t;
        __syncthreads();
    }
    if (i < n) {
        int off = g_bo[blockIdx.x] + sh[tid] - v;
        g_off[i] = off;
        g_cur[i] = off;
    }
}
__global__ void k_fill(const int* __restrict__ src, const int* __restrict__ dst,
                       const int* __restrict__ xidx, int e) {
    int i = blockIdx.x * blockDim.x + threadIdx.x;
    if (i < e) {
        int s = src[i];
        int slot = atomicAdd(&g_cur[dst[i]], 1);
        g_csr[slot] = s;
        g_csrv[slot] = xidx[s];
    }
}

// -------- LN0 lookup table: lut[v] = layernorm(emb[v]) --------
__global__ void lut_kernel(const float* __restrict__ emb, const float* __restrict__ lng,
                           const float* __restrict__ lnb, float* __restrict__ lut) {
    int w = (blockIdx.x * blockDim.x + threadIdx.x) >> 5;
    int lane = threadIdx.x & 31;
    if (w >= 64) return;
    float4 e = *(const float4*)(emb + (size_t)w * 128 + lane * 4);
    float s = e.x + e.y + e.z + e.w;
    float q = e.x * e.x + e.y * e.y + e.z * e.z + e.w * e.w;
    warp_allred2(s, q);
    float mean = s * (1.0f / 128.0f);
    float var  = q * (1.0f / 128.0f) - mean * mean;
    float rs   = rsqrtf(var + 1e-5f);
    float4 g4 = *(const float4*)(lng + lane * 4);
    float4 b4 = *(const float4*)(lnb + lane * 4);
    float4 o;
    o.x = (e.x - mean) * rs * g4.x + b4.x;
    o.y = (e.y - mean) * rs * g4.y + b4.y;
    o.z = (e.z - mean) * rs * g4.z + b4.z;
    o.w = (e.w - mean) * rs * g4.w + b4.w;
    *(float4*)(lut + (size_t)w * 128 + lane * 4) = o;
}

// -------- M = LUT @ w0l^T, R = LUT @ w0r^T  (64x128 each, exact fp32) --------
__global__ void prep_MR(const float* __restrict__ lut, const float* __restrict__ w0l,
                        const float* __restrict__ w0r, float* __restrict__ M,
                        float* __restrict__ R) {
    __shared__ float srow[128];
    int v = blockIdx.x;          // 0..63
    int h = threadIdx.x;         // 0..127
    srow[h] = lut[v * 128 + h];
    __syncthreads();
    float m = 0.f, r = 0.f;
    const float* wl = w0l + h * 128;
    const float* wr = w0r + h * 128;
#pragma unroll 8
    for (int d = 0; d < 128; d++) {
        float x = srow[d];
        m += x * __ldg(wl + d);
        r += x * __ldg(wr + d);
    }
    M[v * 128 + h] = m;
    R[v * 128 + h] = r;
}

// -------- graph-size counts --------
__global__ void cnt_kernel(const int* __restrict__ batch, float* __restrict__ cnt, int n) {
    int i = blockIdx.x * blockDim.x + threadIdx.x;
    if (i < n) atomicAdd(&cnt[batch[i]], 1.0f);
}

// -------- weight prep (layer 1 only): bf16 hi/lo --------
__global__ void prep_wbf(const float* __restrict__ w1l, const float* __restrict__ w1r,
                         unsigned short* __restrict__ wbf) {
    int i = blockIdx.x * blockDim.x + threadIdx.x;
    if (i >= 128 * 256) return;
    int h = i >> 8;
    int d = i & 255;
    float w = (d < 128) ? w1l[h * 128 + d] : w1r[h * 128 + (d - 128)];
    __nv_bfloat16 hi = __float2bfloat16(w);
    __nv_bfloat16 lo = __float2bfloat16(w - __bfloat162float(hi));
    size_t base = (size_t)h * 256 + d;
    wbf[base]         = __bfloat16_as_ushort(hi);
    wbf[base + 32768] = __bfloat16_as_ushort(lo);
}

// ======== layer 0 (exact fp32, no GEMM): x1 = LN1(relu(mean_j M[v_j] + R[xv] + b0)) ========
__global__ void __launch_bounds__(256)
layer0_kernel(const float* __restrict__ M, const float* __restrict__ R,
              const int* __restrict__ xidx, const float* __restrict__ b0,
              const float* __restrict__ lng, const float* __restrict__ lnb,
              float* __restrict__ x1, int n) {
    __shared__ float sM[64 * 128];
    __shared__ float sR[64 * 128];
    __shared__ float sb[128], sg[128], sbt[128];
    int tid = threadIdx.x;
#pragma unroll
    for (int i = 0; i < 8; i++) {
        ((float4*)sM)[tid + i * 256] = ((const float4*)M)[tid + i * 256];
        ((float4*)sR)[tid + i * 256] = ((const float4*)R)[tid + i * 256];
    }
    if (tid < 128) {
        sb[tid]  = b0[tid];
        sg[tid]  = lng[tid];
        sbt[tid] = lnb[tid];
    }
    __syncthreads();
    int lane = tid & 31;
    int wid = tid >> 5;
    int nbase = blockIdx.x * 128 + wid * 16;
    float4 g4 = *(const float4*)(sg + lane * 4);
    float4 t4 = *(const float4*)(sbt + lane * 4);
    float4 b4 = *(const float4*)(sb + lane * 4);
#pragma unroll 1
    for (int ni = 0; ni < 16; ni++) {
        int node = nbase + ni;
        if (node >= n) break;
        int beg = __ldg(&g_off[node]);
        int end = __ldg(&g_off[node + 1]);
        float4 acc = make_float4(0.f, 0.f, 0.f, 0.f);
        for (int j0 = beg; j0 < end; j0 += 32) {
            int vid = 0;
            if (j0 + lane < end) vid = __ldg(&g_csrv[j0 + lane]);
            int cnt = end - j0; if (cnt > 32) cnt = 32;
            for (int t = 0; t < cnt; t++) {
                int v = __shfl_sync(0xffffffffu, vid, t);
                float4 e = *(const float4*)(sM + v * 128 + lane * 4);
                acc.x += e.x; acc.y += e.y; acc.z += e.z; acc.w += e.w;
            }
        }
        float inv = 1.0f / fmaxf((float)(end - beg), 1.0f);
        int xv = __ldg(xidx + node);
        float4 r4 = *(const float4*)(sR + xv * 128 + lane * 4);
        float v0 = fmaxf(acc.x * inv + r4.x + b4.x, 0.f);
        float v1 = fmaxf(acc.y * inv + r4.y + b4.y, 0.f);
        float v2 = fmaxf(acc.z * inv + r4.z + b4.z, 0.f);
        float v3 = fmaxf(acc.w * inv + r4.w + b4.w, 0.f);
        float s = v0 + v1 + v2 + v3;
        float q = v0 * v0 + v1 * v1 + v2 * v2 + v3 * v3;
        warp_allred2(s, q);
        float mean = s * (1.0f / 128.0f);
        float var  = q * (1.0f / 128.0f) - mean * mean;
        float rs   = rsqrtf(var + 1e-5f);
        float4 o;
        o.x = (v0 - mean) * rs * g4.x + t4.x;
        o.y = (v1 - mean) * rs * g4.y + t4.y;
        o.z = (v2 - mean) * rs * g4.z + t4.z;
        o.w = (v3 - mean) * rs * g4.w + t4.w;
        *(float4*)(x1 + (size_t)node * 128 + lane * 4) = o;
    }
}

// ======== gather L1: mean over neighbor rows of x (warp per node, 2-way ILP) ========
__global__ void gather_mean(const float* __restrict__ x, float* __restrict__ agg, int n) {
    int w = (blockIdx.x * blockDim.x + threadIdx.x) >> 5;
    int lane = threadIdx.x & 31;
    if (w >= n) return;
    int beg = __ldg(&g_off[w]);
    int end = __ldg(&g_off[w + 1]);
    float4 acc0 = make_float4(0.f, 0.f, 0.f, 0.f);
    float4 acc1 = make_float4(0.f, 0.f, 0.f, 0.f);
    for (int j0 = beg; j0 < end; j0 += 32) {
        int nid = 0;
        if (j0 + lane < end) nid = __ldg(&g_csr[j0 + lane]);
        int cnt = end - j0; if (cnt > 32) cnt = 32;
        int t = 0;
        for (; t + 1 < cnt; t += 2) {
            int s0 = __shfl_sync(0xffffffffu, nid, t);
            int s1 = __shfl_sync(0xffffffffu, nid, t + 1);
            float4 v0 = *(const float4*)(x + (size_t)s0 * 128 + lane * 4);
            float4 v1 = *(const float4*)(x + (size_t)s1 * 128 + lane * 4);
            acc0.x += v0.x; acc0.y += v0.y; acc0.z += v0.z; acc0.w += v0.w;
            acc1.x += v1.x; acc1.y += v1.y; acc1.z += v1.z; acc1.w += v1.w;
        }
        if (t < cnt) {
            int s0 = __shfl_sync(0xffffffffu, nid, t);
            float4 v0 = *(const float4*)(x + (size_t)s0 * 128 + lane * 4);
            acc0.x += v0.x; acc0.y += v0.y; acc0.z += v0.z; acc0.w += v0.w;
        }
    }
    float inv = 1.0f / fmaxf((float)(end - beg), 1.0f);
    *(float4*)(agg + (size_t)w * 128 + lane * 4) =
        make_float4((acc0.x + acc1.x) * inv, (acc0.y + acc1.y) * inv,
                    (acc0.z + acc1.z) * inv, (acc0.w + acc1.w) * inv);
}

// ======== HMMA bf16x3 SAGE linear (layer 1), BM=64 x BN=128, 2 CTAs/SM ========
// half0 A = agg rows, half1 A = x1 rows. Epilogue: bias+relu, fused pooling (no out write).
#define ROWA 272
#define OFF_AHI    0
#define OFF_ALO    17408
#define OFF_BHI    34816
#define OFF_BLO    69632
#define OFF_GID    104448            // 64 ints
#define SMEM_TOTAL 104704

__global__ void __launch_bounds__(256, 2)
sage_mma(const float* __restrict__ agg, const float* __restrict__ xin,
         const unsigned short* __restrict__ wbf, const float* __restrict__ bias,
         const int* __restrict__ batch, float* __restrict__ pool, int n) {
    extern __shared__ char smem[];
    const uint32_t sb = smem_u32(smem);
    const int tid  = threadIdx.x;
    const int wid  = tid >> 5;
    const int lane = tid & 31;
    const int row0 = blockIdx.x * 64;
    const int wm   = wid & 1;
    const int wn   = wid >> 1;

    float acc[2][4][4];
#pragma unroll
    for (int mt = 0; mt < 2; mt++)
#pragma unroll
        for (int nt = 0; nt < 4; nt++)
#pragma unroll
            for (int j = 0; j < 4; j++) acc[mt][nt][j] = 0.f;

    const int lm = lane >> 3;
    const int lr = lane & 7;
    const uint32_t aRow = (uint32_t)(wm * 32 + (lm & 1) * 8 + lr);
    const uint32_t aKof = (uint32_t)((lm >> 1) * 16);
    const uint32_t bN   = (uint32_t)(wn * 32 + (lm >> 1) * 8 + lr);
    const uint32_t bKof = (uint32_t)((lm & 1) * 16);

#pragma unroll 1
    for (int half = 0; half < 2; half++) {
        // ---- fill B hi/lo for this K-half ----
#pragma unroll
        for (int it = 0; it < 16; it++) {
            int idx = it * 256 + tid;
            int part = idx >> 11;
            int rem = idx & 2047;
            int row = rem >> 4;
            int ch = rem & 15;
            uint4 v = *(const uint4*)(wbf + part * 32768 + row * 256 + half * 128 + ch * 8);
            *(uint4*)(smem + OFF_BHI + part * 34816 + row * ROWA + ch * 16) = v;
        }
        // ---- fill A hi/lo for this K-half (coalesced rows) ----
        const float* srcA = half ? xin : agg;
#pragma unroll
        for (int it = 0; it < 8; it++) {
            int idx = it * 256 + tid;
            int row = idx >> 5;
            int col = (idx & 31) * 4;
            float4 v = make_float4(0.f, 0.f, 0.f, 0.f);
            int grow = row0 + row;
            if (grow < n) v = *(const float4*)(srcA + (size_t)grow * 128 + col);
            float hx = __bfloat162float(__float2bfloat16(v.x));
            float hy = __bfloat162float(__float2bfloat16(v.y));
            float hz = __bfloat162float(__float2bfloat16(v.z));
            float hw = __bfloat162float(__float2bfloat16(v.w));
            __nv_bfloat162 h0 = __floats2bfloat162_rn(hx, hy);
            __nv_bfloat162 h1 = __floats2bfloat162_rn(hz, hw);
            __nv_bfloat162 l0 = __floats2bfloat162_rn(v.x - hx, v.y - hy);
            __nv_bfloat162 l1 = __floats2bfloat162_rn(v.z - hz, v.w - hw);
            uint2 ph, pl;
            ph.x = *reinterpret_cast<unsigned*>(&h0);
            ph.y = *reinterpret_cast<unsigned*>(&h1);
            pl.x = *reinterpret_cast<unsigned*>(&l0);
            pl.y = *reinterpret_cast<unsigned*>(&l1);
            *(uint2*)(smem + OFF_AHI + row * ROWA + col * 2) = ph;
            *(uint2*)(smem + OFF_ALO + row * ROWA + col * 2) = pl;
        }
        __syncthreads();

        // ---- 8 k16-steps, 3 products ----
#pragma unroll
        for (int kk = 0; kk < 8; kk++) {
            const uint32_t kB = (uint32_t)kk * 32;
            const uint32_t aOff = aRow * ROWA + aKof + kB;
            const uint32_t bOff = bN * ROWA + bKof + kB;
            uint32_t ah[2][4], al[2][4], bh[2][4], bl[2][4];
#pragma unroll
            for (int mt = 0; mt < 2; mt++) {
                ldsm_x4(ah[mt][0], ah[mt][1], ah[mt][2], ah[mt][3],
                        sb + OFF_AHI + aOff + (uint32_t)mt * 16u * ROWA);
                ldsm_x4(al[mt][0], al[mt][1], al[mt][2], al[mt][3],
                        sb + OFF_ALO + aOff + (uint32_t)mt * 16u * ROWA);
            }
#pragma unroll
            for (int nb = 0; nb < 2; nb++) {
                ldsm_x4(bh[nb][0], bh[nb][1], bh[nb][2], bh[nb][3],
                        sb + OFF_BHI + bOff + (uint32_t)nb * 16u * ROWA);
                ldsm_x4(bl[nb][0], bl[nb][1], bl[nb][2], bl[nb][3],
                        sb + OFF_BLO + bOff + (uint32_t)nb * 16u * ROWA);
            }
#pragma unroll
            for (int mt = 0; mt < 2; mt++)
#pragma unroll
                for (int nb = 0; nb < 2; nb++) {
                    mma16816(acc[mt][nb * 2 + 0], ah[mt], bh[nb][0], bh[nb][1]);
                    mma16816(acc[mt][nb * 2 + 1], ah[mt], bh[nb][2], bh[nb][3]);
                    mma16816(acc[mt][nb * 2 + 0], ah[mt], bl[nb][0], bl[nb][1]);
                    mma16816(acc[mt][nb * 2 + 1], ah[mt], bl[nb][2], bl[nb][3]);
                    mma16816(acc[mt][nb * 2 + 0], al[mt], bh[nb][0], bh[nb][1]);
                    mma16816(acc[mt][nb * 2 + 1], al[mt], bh[nb][2], bh[nb][3]);
                }
        }
        __syncthreads();
    }

    // ---- stage: bias + relu into fp32 smem (stride 132, overlays A/B region) ----
    float* stage = (float*)smem;
    {
        const int cBase = wn * 32 + (lane & 3) * 2;
#pragma unroll
        for (int nt = 0; nt < 4; nt++) {
            int col = cBase + nt * 8;
            float b0 = __ldg(bias + col), b1 = __ldg(bias + col + 1);
#pragma unroll
            for (int mt = 0; mt < 2; mt++) {
                int r0 = wm * 32 + mt * 16 + (lane >> 2);
                float2 v0, v1;
                v0.x = fmaxf(acc[mt][nt][0] + b0, 0.f);
                v0.y = fmaxf(acc[mt][nt][1] + b1, 0.f);
                v1.x = fmaxf(acc[mt][nt][2] + b0, 0.f);
                v1.y = fmaxf(acc[mt][nt][3] + b1, 0.f);
                *(float2*)(stage + r0 * 132 + col)       = v0;
                *(float2*)(stage + (r0 + 8) * 132 + col) = v1;
            }
        }
    }
    if (tid < 64) {
        int grow = row0 + tid;
        ((int*)(smem + OFF_GID))[tid] = (grow < n) ? __ldg(batch + grow) : -1;
    }
    __syncthreads();

    // ---- fused pooling: run-length over sorted batch within the tile ----
    if (tid < 128) {
        const int* sgid = (const int*)(smem + OFF_GID);
        float a = 0.f;
        int cur = sgid[0];
#pragma unroll 1
        for (int r = 0; r < 64; r++) {
            int gid = sgid[r];
            if (gid != cur) {
                if (cur >= 0) atomicAdd(&pool[(size_t)cur * 128 + tid], a);
                a = 0.f; cur = gid;
            }
            if (gid >= 0) a += stage[r * 132 + tid];
        }
        if (cur >= 0) atomicAdd(&pool[(size_t)cur * 128 + tid], a);
    }
}

// -------- MLP head --------
__global__ void mlp_kernel(const float* __restrict__ sums, const float* __restrict__ cnts,
                           const float* __restrict__ w1, const float* __restrict__ b1,
                           const float* __restrict__ w2, const float* __restrict__ b2,
                           float* __restrict__ out) {
    __shared__ float sg[128];
    __shared__ float sh[64];
    int g = blockIdx.x;
    int t = threadIdx.x;   // 64
    float inv = 1.0f / fmaxf(__ldg(cnts + g), 1.0f);
    sg[t]      = sums[(size_t)g * 128 + t] * inv;
    sg[t + 64] = sums[(size_t)g * 128 + t + 64] * inv;
    __syncthreads();
    float h = b1[t];
#pragma unroll
    for (int d = 0; d < 128; d++) h += w1[t * 128 + d] * sg[d];
    sh[t] = fmaxf(h, 0.f);
    __syncthreads();
    if (t < 2) {
        float o = b2[t];
#pragma unroll
        for (int d = 0; d < 64; d++) o += w2[t * 64 + d] * sh[d];
        out[g * 2 + t] = o;
    }
}

// -------- launch --------
extern "C" void kernel_launch(void* const* d_in, const int* in_sizes, int n_in,
                              void* d_out, int out_size) {
    const int*   x_idx = (const int*)d_in[0];
    const int*   eidx  = (const int*)d_in[1];
    const int*   batch = (const int*)d_in[2];
    const float* emb   = (const float*)d_in[3];
    const float* ln0g  = (const float*)d_in[4];
    const float* ln0b  = (const float*)d_in[5];
    const float* w0l   = (const float*)d_in[6];
    const float* b0l   = (const float*)d_in[7];
    const float* w0r   = (const float*)d_in[8];
    const float* ln1g  = (const float*)d_in[9];
    const float* ln1b  = (const float*)d_in[10];
    const float* w1l   = (const float*)d_in[11];
    const float* b1l   = (const float*)d_in[12];
    const float* w1r   = (const float*)d_in[13];
    const float* mw1   = (const float*)d_in[14];
    const float* mb1   = (const float*)d_in[15];
    const float* mw2   = (const float*)d_in[16];
    const float* mb2   = (const float*)d_in[17];
    float* out = (float*)d_out;

    int n = in_sizes[0];
    int e = in_sizes[1] / 2;
    const int* src = eidx;
    const int* dst = eidx + e;

    float *x1, *agg, *lut, *Mt, *Rt, *pool, *cnt;
    unsigned short* wbf;
    int* degi;
    (void)cudaGetSymbolAddress((void**)&x1,   g_x1);
    (void)cudaGetSymbolAddress((void**)&agg,  g_agg);
    (void)cudaGetSymbolAddress((void**)&lut,  g_lut);
    (void)cudaGetSymbolAddress((void**)&Mt,   g_M);
    (void)cudaGetSymbolAddress((void**)&Rt,   g_R);
    (void)cudaGetSymbolAddress((void**)&wbf,  g_wbf);
    (void)cudaGetSymbolAddress((void**)&pool, g_pool);
    (void)cudaGetSymbolAddress((void**)&cnt,  g_cnt);
    (void)cudaGetSymbolAddress((void**)&degi, g_degi);

    (void)cudaFuncSetAttribute(sage_mma, cudaFuncAttributeMaxDynamicSharedMemorySize,
                               SMEM_TOTAL);

    cudaMemsetAsync(degi, 0, (size_t)n * sizeof(int));
    cudaMemsetAsync(pool, 0, (size_t)GG * 128 * sizeof(float));
    cudaMemsetAsync(cnt,  0, (size_t)GG * sizeof(float));

    // CSR build (once; reused by both layers)
    int nb = (n + 1023) / 1024;
    k_count<<<(e + 255) / 256, 256>>>(dst, e);
    k_bsum<<<nb, 1024>>>(n);
    k_bscan<<<1, 32>>>(nb, n);
    k_scan<<<nb, 1024>>>(n);
    k_fill<<<(e + 255) / 256, 256>>>(src, dst, x_idx, e);

    lut_kernel<<<8, 256>>>(emb, ln0g, ln0b, lut);
    prep_MR<<<64, 128>>>(lut, w0l, w0r, Mt, Rt);
    prep_wbf<<<128, 256>>>(w1l, w1r, wbf);
    cnt_kernel<<<(n + 255) / 256, 256>>>(batch, cnt, n);

    // layer 0: table-based (exact fp32), no GEMM
    layer0_kernel<<<(n + 127) / 128, 256>>>(Mt, Rt, x_idx, b0l, ln1g, ln1b, x1, n);
    // layer 1: gather + GEMM + fused pooling
    gather_mean<<<(n * 32 + 255) / 256, 256>>>(x1, agg, n);
    sage_mma<<<(n + 63) / 64, 256, SMEM_TOTAL>>>(agg, x1, wbf, b1l, batch, pool, n);
    // head
    mlp_kernel<<<GG, 64>>>(pool, cnt, mw1, mb1, mw2, mb2, out);
}